// round 5
// baseline (speedup 1.0000x reference)
#include <cuda_runtime.h>
#include <cuda_bf16.h>

// GRU final-hidden: B=8192 independent scans, T<=2048, I=1, H=3.
// One thread per batch element; recurrence fully in registers.
// Occupancy is capped by B (256 warps over 592 SMSPs), so per-warp per-step
// cycle cost is everything. Floors: 9 MUFU.TANH/step @ rt 8 = 72 cyc,
// ~62 instr issue, ~60 cyc h->h chain. This version removes the per-step
// masking and hoists all x-only FMAs to chunk start so the scheduler can
// fill the tanh latency bubbles.

__device__ __forceinline__ float tanh_fast(float u) {
    float y;
    asm("tanh.approx.f32 %0, %1;" : "=f"(y) : "f"(u));
    return y;
}

__device__ __forceinline__ float fsig_acc(float u) {
    // accurate sigmoid, used only for the 3 final outputs (off hot path)
    float e = __expf(-u);
    return __fdividef(1.0f, 1.0f + e);
}

__global__ __launch_bounds__(64, 1) void gru_seq_kernel(
    const float* __restrict__ x,      // [B, T, 1]
    const int*   __restrict__ lens,   // [B]
    const float* __restrict__ h0,     // [B, 3]
    const float* __restrict__ Wih,    // [9, 1]
    const float* __restrict__ Whh,    // [9, 3]
    const float* __restrict__ bih,    // [9]
    const float* __restrict__ bhh,    // [9]
    float* __restrict__ out,          // [1, B, 3]
    int B, int T)
{
    int b = blockIdx.x * blockDim.x + threadIdx.x;
    if (b >= B) return;
    int len = lens[b];
    if (len < 1) len = 1;
    if (len > T) len = T;

    // r/z gate weights pre-scaled by 0.5: sigmoid(u) = 0.5*tanh(0.5u)+0.5.
    float wxr[3], wxz[3], wxn[3];
    float whr[3][3], whz[3][3], whn[3][3];
    float br[3], bz[3], bxn[3], bhn[3];
#pragma unroll
    for (int j = 0; j < 3; ++j) {
        wxr[j] = 0.5f * Wih[j];
        wxz[j] = 0.5f * Wih[3 + j];
        wxn[j] = Wih[6 + j];
#pragma unroll
        for (int k = 0; k < 3; ++k) {
            whr[j][k] = 0.5f * Whh[j * 3 + k];
            whz[j][k] = 0.5f * Whh[(3 + j) * 3 + k];
            whn[j][k] = Whh[(6 + j) * 3 + k];
        }
        br[j]  = 0.5f * (bih[j]     + bhh[j]);
        bz[j]  = 0.5f * (bih[3 + j] + bhh[3 + j]);
        bxn[j] = bih[6 + j];
        bhn[j] = bhh[6 + j];
    }

    float h[3];
#pragma unroll
    for (int j = 0; j < 3; ++j) h[j] = h0[b * 3 + j];

    // One GRU step with precomputed x-projections (cr/cz/cn = w*x + b).
    // Unmasked: caller guarantees this step index < len.
    auto step = [&](const float* cr, const float* cz, const float* cn) {
        float r[3], z[3], n[3];
#pragma unroll
        for (int j = 0; j < 3; ++j) {
            float ur = fmaf(whr[j][2], h[2], fmaf(whr[j][1], h[1], fmaf(whr[j][0], h[0], cr[j])));
            float uz = fmaf(whz[j][2], h[2], fmaf(whz[j][1], h[1], fmaf(whz[j][0], h[0], cz[j])));
            float hn = fmaf(whn[j][2], h[2], fmaf(whn[j][1], h[1], fmaf(whn[j][0], h[0], bhn[j])));
            r[j] = fmaf(tanh_fast(ur), 0.5f, 0.5f);   // sigmoid
            z[j] = fmaf(tanh_fast(uz), 0.5f, 0.5f);   // sigmoid
            n[j] = tanh_fast(fmaf(r[j], hn, cn[j]));
        }
#pragma unroll
        for (int j = 0; j < 3; ++j)
            h[j] = fmaf(z[j], h[j] - n[j], n[j]);      // h' = n + z*(h-n)
    };

    // x row: contiguous T floats, 16B-aligned.
    const float4* xp = reinterpret_cast<const float4*>(x + (size_t)b * T);
    int nFull   = len >> 2;         // chunks with all 4 steps active
    int rem     = len & 3;          // active steps in the tail chunk
    int nChunks = (len + 3) >> 2;

    float4 cur = xp[0];
    for (int c = 0; c < nFull; ++c) {
        float4 nxt = (c + 1 < nChunks) ? xp[c + 1] : cur;   // prefetch
        float xs[4] = {cur.x, cur.y, cur.z, cur.w};

        // All x-only projections for the 4 steps: 36 independent FMAs the
        // scheduler can interleave into the tanh latency of earlier steps.
        float cr[4][3], cz[4][3], cn[4][3];
#pragma unroll
        for (int k = 0; k < 4; ++k)
#pragma unroll
            for (int j = 0; j < 3; ++j) {
                cr[k][j] = fmaf(wxr[j], xs[k], br[j]);
                cz[k][j] = fmaf(wxz[j], xs[k], bz[j]);
                cn[k][j] = fmaf(wxn[j], xs[k], bxn[j]);
            }

#pragma unroll
        for (int k = 0; k < 4; ++k) step(cr[k], cz[k], cn[k]);
        cur = nxt;
    }

    // Masked tail: at most 3 steps.
    if (rem) {
        float xs[3] = {cur.x, cur.y, cur.z};
#pragma unroll
        for (int k = 0; k < 3; ++k) {
            if (k < rem) {
                float cr[3], cz[3], cn[3];
#pragma unroll
                for (int j = 0; j < 3; ++j) {
                    cr[j] = fmaf(wxr[j], xs[k], br[j]);
                    cz[j] = fmaf(wxz[j], xs[k], bz[j]);
                    cn[j] = fmaf(wxn[j], xs[k], bxn[j]);
                }
                step(cr, cz, cn);
            }
        }
    }

    // Output = sigmoid(hT), layout [1, B, H].
#pragma unroll
    for (int j = 0; j < 3; ++j) out[b * 3 + j] = fsig_acc(h[j]);
}

extern "C" void kernel_launch(void* const* d_in, const int* in_sizes, int n_in,
                              void* d_out, int out_size)
{
    const float* x   = (const float*)d_in[0];
    const int*   len = (const int*)  d_in[1];
    const float* h0  = (const float*)d_in[2];
    const float* Wih = (const float*)d_in[3];
    const float* Whh = (const float*)d_in[4];
    const float* bih = (const float*)d_in[5];
    const float* bhh = (const float*)d_in[6];
    float* out = (float*)d_out;

    int B = in_sizes[1];            // seq_lengths is [B]
    int T = in_sizes[0] / B;        // x is [B, T, 1]

    const int block = 64;
    int grid = (B + block - 1) / block;
    gru_seq_kernel<<<grid, block>>>(x, len, h0, Wih, Whh, bih, bhh, out, B, T);
}